// round 13
// baseline (speedup 1.0000x reference)
#include <cuda_runtime.h>
#include <cuda_bf16.h>
#include <cuda_fp16.h>
#include <cstdint>

// Problem constants
#define BATCH 32
#define TT    1024
#define DD    256
#define KK    1024
#define NN    (BATCH*TT)
#define DT    (DD*TT)

#define OUT_Q_OFF    0
#define OUT_LOSS_OFF 8388608
#define OUT_IDX_OFF  8388609

#define EPS_SEL 4e-3f

typedef unsigned long long ull;

// -------- device scratch (no allocations allowed) --------
__device__ __half g_A2[(size_t)NN * DD];       // token-major fp16 latents
__device__ __half g_B2[(size_t)KK * DD];       // fp16 codebook
__device__ float  g_Xt[(size_t)NN * DD];       // token-major fp32 latents
__device__ uint4  g_tc[(size_t)NN * 16];       // per (token, 64-tile): tmin + 3 cands
__device__ unsigned char g_tcnt[(size_t)NN * 16];  // per-tile candidate count
__device__ float  g_wnorm[KK];
__device__ float  g_xnorm[NN];
__device__ unsigned g_idx[NN];
__device__ double g_loss;
__device__ unsigned g_qdone;

// -------- PTX helpers --------
__device__ __forceinline__ uint32_t smem_u32(const void* p) {
    uint32_t a;
    asm("{ .reg .u64 t; cvta.to.shared.u64 t, %1; cvt.u32.u64 %0, t; }"
        : "=r"(a) : "l"(p));
    return a;
}
__device__ __forceinline__ void cp_async16(uint32_t s, const void* g) {
    asm volatile("cp.async.cg.shared.global [%0], [%1], 16;" :: "r"(s), "l"(g));
}
#define CP_COMMIT() asm volatile("cp.async.commit_group;")
#define CP_WAIT1()  asm volatile("cp.async.wait_group 1;")
#define CP_WAIT0()  asm volatile("cp.async.wait_group 0;")

#define LDSM_X4(r0, r1, r2, r3, addr) \
    asm volatile("ldmatrix.sync.aligned.m8n8.x4.shared.b16 {%0,%1,%2,%3}, [%4];" \
        : "=r"(r0), "=r"(r1), "=r"(r2), "=r"(r3) : "r"(addr))

#define MMA_F16(c, a, b0, b1) \
    asm volatile("mma.sync.aligned.m16n8k16.row.col.f32.f16.f16.f32 " \
        "{%0,%1,%2,%3}, {%4,%5,%6,%7}, {%8,%9}, {%0,%1,%2,%3};" \
        : "+f"((c)[0]), "+f"((c)[1]), "+f"((c)[2]), "+f"((c)[3]) \
        : "r"((a)[0]), "r"((a)[1]), "r"((a)[2]), "r"((a)[3]), "r"(b0), "r"(b1))

// ---------------------------------------------------------
// prep B: fp16 codebook + wnorm; zero loss + counter
__global__ void vq_prep_b_kernel(const float* __restrict__ cb) {
    __shared__ double sred[256];
    int k = blockIdx.x, d = threadIdx.x;
    float w = cb[k * DD + d];
    g_B2[(size_t)k * DD + d] = __float2half_rn(w);
    sred[d] = (double)w * (double)w;
    __syncthreads();
    for (int s = 128; s > 0; s >>= 1) {
        if (d < s) sred[d] += sred[d + s];
        __syncthreads();
    }
    if (d == 0) {
        g_wnorm[k] = (float)sred[0];
        if (k == 0) { g_loss = 0.0; g_qdone = 0; }
    }
}

// prep A: transpose latents to token-major fp32 + fp16, fused xnorm (fp64).
__global__ void __launch_bounds__(256)
vq_prep_a_kernel(const float* __restrict__ lat) {
    __shared__ float  s[256 * 33];
    __shared__ double pr[256];
    const int tid = threadIdx.x;
    const int b   = blockIdx.x >> 5;
    const int t0  = (blockIdx.x & 31) << 5;

    #pragma unroll
    for (int i = tid; i < 2048; i += 256) {
        int d = i >> 3, tq = i & 7;
        float4 v = *(const float4*)(lat + ((size_t)b * DD + d) * TT + t0 + tq * 4);
        s[d * 33 + tq * 4 + 0] = v.x;
        s[d * 33 + tq * 4 + 1] = v.y;
        s[d * 33 + tq * 4 + 2] = v.z;
        s[d * 33 + tq * 4 + 3] = v.w;
    }
    __syncthreads();

    const int d = tid;
    #pragma unroll 4
    for (int tl = 0; tl < 32; tl++) {
        size_t n = (size_t)b * TT + t0 + tl;
        float x = s[d * 33 + tl];
        g_A2[n * DD + d] = __float2half_rn(x);
        g_Xt[n * DD + d] = x;
    }

    const int tk = tid & 31, dg = tid >> 5;
    double ssum = 0.0;
    #pragma unroll 8
    for (int dd = 0; dd < 32; dd++) {
        float v = s[(dg * 32 + dd) * 33 + tk];
        ssum += (double)v * (double)v;
    }
    pr[tid] = ssum;
    __syncthreads();
    if (tid < 32) {
        double tot = 0.0;
        #pragma unroll
        for (int j = 0; j < 8; j++) tot += pr[j * 32 + tid];
        g_xnorm[b * TT + t0 + tid] = (float)tot;
    }
}

// ---------------------------------------------------------
// main GEMM: CTA 128 tokens x 128 codes, K=256 in 4 chunks of 64,
// mma.sync m16n8k16 fp16, double-buffered cp.async tiles (SW128 swizzle).
// Epilogue: per (token, 64-code tile) min + candidate extraction (no g_s).
#define SM_WN    65536
#define SM_TOTM  66048

__device__ __forceinline__ void issue_chunk(uint32_t sb, int bufsel, int chunk,
                                            int n0, int kb, int tid) {
    uint32_t Ab = sb + (uint32_t)bufsel * 32768u;
    #pragma unroll
    for (int u = 0; u < 4; u++) {
        int j = tid + u * 256;
        int r = j >> 3, g8 = j & 7;
        cp_async16(Ab + (uint32_t)(r * 128 + ((g8 * 16) ^ ((r & 7) << 4))),
                   g_A2 + (size_t)(n0 + r) * DD + chunk * 64 + g8 * 8);
    }
    #pragma unroll
    for (int u = 0; u < 4; u++) {
        int j = tid + u * 256;
        int r = j >> 3, g8 = j & 7;
        cp_async16(Ab + 16384u + (uint32_t)(r * 128 + ((g8 * 16) ^ ((r & 7) << 4))),
                   g_B2 + (size_t)(kb + r) * DD + chunk * 64 + g8 * 8);
    }
}

__global__ void __launch_bounds__(256, 2)
vq_mma_kernel() {
    extern __shared__ char smc[];
    const uint32_t sb = smem_u32(smc);
    float* wn_s = (float*)(smc + SM_WN);

    const int tid  = threadIdx.x;
    const int lane = tid & 31;
    const int warp = tid >> 5;
    const int wm   = warp >> 1;        // 0..3
    const int wnn  = warp & 1;         // 0..1
    const int n0   = blockIdx.x << 7;  // token base
    const int kb   = blockIdx.y << 7;  // code base

    if (tid < 128) wn_s[tid] = g_wnorm[kb + tid];

    issue_chunk(sb, 0, 0, n0, kb, tid); CP_COMMIT();
    issue_chunk(sb, 1, 1, n0, kb, tid); CP_COMMIT();

    float acc[2][8][4];
    #pragma unroll
    for (int i = 0; i < 2; i++)
        #pragma unroll
        for (int j = 0; j < 8; j++)
            #pragma unroll
            for (int e = 0; e < 4; e++) acc[i][j][e] = 0.0f;

    const int arow   = (lane & 7) | (((lane >> 3) & 1) << 3);
    const int akoffB = (lane >> 4) << 4;
    const int brow   = (lane & 7) | ((lane >> 4) << 3);
    const int bkoffB = ((lane >> 3) & 1) << 4;

    for (int c = 0; c < 4; c++) {
        if (c < 3) { CP_WAIT1(); } else { CP_WAIT0(); }
        __syncthreads();

        uint32_t Ab = sb + (uint32_t)(c & 1) * 32768u;
        uint32_t Bb = Ab + 16384u;

        #pragma unroll
        for (int k16 = 0; k16 < 4; k16++) {
            uint32_t a[2][4];
            #pragma unroll
            for (int mt = 0; mt < 2; mt++) {
                int r = wm * 32 + mt * 16 + arow;
                uint32_t ad = Ab + (uint32_t)(r * 128 +
                              ((k16 * 32 + akoffB) ^ ((r & 7) << 4)));
                LDSM_X4(a[mt][0], a[mt][1], a[mt][2], a[mt][3], ad);
            }
            uint32_t bf[8][2];
            #pragma unroll
            for (int p = 0; p < 4; p++) {
                int nl = wnn * 64 + p * 16 + brow;
                uint32_t bd = Bb + (uint32_t)(nl * 128 +
                              ((k16 * 32 + bkoffB) ^ ((nl & 7) << 4)));
                LDSM_X4(bf[2 * p][0], bf[2 * p][1], bf[2 * p + 1][0], bf[2 * p + 1][1], bd);
            }
            #pragma unroll
            for (int mt = 0; mt < 2; mt++)
                #pragma unroll
                for (int n8 = 0; n8 < 8; n8++)
                    MMA_F16(acc[mt][n8], a[mt], bf[n8][0], bf[n8][1]);
        }
        __syncthreads();
        if (c < 2) { issue_chunk(sb, c & 1, c + 2, n0, kb, tid); CP_COMMIT(); }
    }

    // ---- epilogue: per (row, 64-code tile): tmin + <=3 candidates ----
    const int g    = lane >> 2;
    const int qc   = lane & 3;
    const int qb   = lane & ~3;
    const int tile = (kb >> 6) + wnn;      // global 64-code tile index 0..15
    #pragma unroll
    for (int mt = 0; mt < 2; mt++) {
        #pragma unroll
        for (int h = 0; h < 2; h++) {
            int rl = wm * 32 + mt * 16 + h * 8 + g;
            size_t tci = (size_t)(n0 + rl) * 16 + tile;
            unsigned hb[16];
            float v[16];
            float vmin = 6.0e4f;
            #pragma unroll
            for (int n8 = 0; n8 < 8; n8++) {
                #pragma unroll
                for (int e = 0; e < 2; e++) {
                    int cl = wnn * 64 + n8 * 8 + qc * 2 + e;
                    float s = __fmaf_rn(-2.0f, acc[mt][n8][h * 2 + e], wn_s[cl]);
                    __half hh = __float2half_rn(s);
                    int idx = n8 * 2 + e;
                    hb[idx] = (unsigned)__half_as_ushort(hh);
                    v[idx] = __half2float(hh);
                    vmin = fminf(vmin, v[idx]);
                }
            }
            float m = fminf(vmin, __shfl_xor_sync(0xFFFFFFFFu, vmin, 1));
            m = fminf(m, __shfl_xor_sync(0xFFFFFFFFu, m, 2));
            float th = m + EPS_SEL;
            unsigned mask = 0;
            #pragma unroll
            for (int i = 0; i < 16; i++) if (v[i] <= th) mask |= 1u << i;
            int cntl = __popc(mask);
            int c0 = __shfl_sync(0xFFFFFFFFu, cntl, qb + 0);
            int c1 = __shfl_sync(0xFFFFFFFFu, cntl, qb + 1);
            int c2 = __shfl_sync(0xFFFFFFFFu, cntl, qb + 2);
            int c3 = __shfl_sync(0xFFFFFFFFu, cntl, qb + 3);
            int total = c0 + c1 + c2 + c3;
            if (qc == 0) {
                ((uint32_t*)&g_tc[tci])[0] = __float_as_uint(m);
                g_tcnt[tci] = (unsigned char)min(total, 255);
            }
            if (total <= 3 && cntl) {
                int slot = (qc > 0 ? c0 : 0) + (qc > 1 ? c1 : 0) + (qc > 2 ? c2 : 0);
                unsigned mm = mask;
                while (mm) {
                    int bpos = __ffs(mm) - 1; mm &= mm - 1;
                    int n8 = bpos >> 1, e = bpos & 1;
                    unsigned kg = (unsigned)(kb + wnn * 64 + n8 * 8 + qc * 2 + e);
                    ((uint32_t*)&g_tc[tci])[1 + slot] = (kg << 16) | hb[bpos];
                    slot++;
                }
            }
        }
    }
}

// ---------------------------------------------------------
// select: warp per token. Read 16 per-tile entries (256 B), warp min,
// filter stored candidates to the global threshold; single candidate ->
// done; else exact fp32 recheck (reference dist formula + packed (dist,k)
// first-index tie-break); overflow tiles recheck all 64 codes.
__device__ __forceinline__ ull recheck_one(int k, float xn, float4 xa, float4 xb,
                                           const float* __restrict__ cb) {
    const float4* wr = (const float4*)(cb + (size_t)k * DD);
    int lane = threadIdx.x & 31;
    float4 wa = wr[lane];
    float4 wb = wr[32 + lane];
    float s = 0.0f;
    s = __fmaf_rn(xa.x, wa.x, s); s = __fmaf_rn(xa.y, wa.y, s);
    s = __fmaf_rn(xa.z, wa.z, s); s = __fmaf_rn(xa.w, wa.w, s);
    s = __fmaf_rn(xb.x, wb.x, s); s = __fmaf_rn(xb.y, wb.y, s);
    s = __fmaf_rn(xb.z, wb.z, s); s = __fmaf_rn(xb.w, wb.w, s);
    #pragma unroll
    for (int o = 16; o; o >>= 1) s = __fadd_rn(s, __shfl_xor_sync(0xFFFFFFFFu, s, o));
    float dist = __fadd_rn(__fmaf_rn(-2.0f, s, xn), g_wnorm[k]);
    return ((ull)__float_as_uint(dist) << 32) | (unsigned)k;
}

__global__ void __launch_bounds__(256)
vq_select_kernel(const float* __restrict__ cb) {
    const int wid  = threadIdx.x >> 5;
    const int lane = threadIdx.x & 31;
    const int n    = blockIdx.x * 8 + wid;

    uint4 e = make_uint4(0, 0, 0, 0);
    float tmin = 6.0e4f;
    int cnt = 0;
    if (lane < 16) {
        e = g_tc[(size_t)n * 16 + lane];
        tmin = __uint_as_float(e.x);
        cnt = g_tcnt[(size_t)n * 16 + lane];
    }
    float gm = tmin;
    #pragma unroll
    for (int o = 16; o; o >>= 1) gm = fminf(gm, __shfl_xor_sync(0xFFFFFFFFu, gm, o));
    const float th = gm + EPS_SEL;

    const bool pass = (lane < 16) && (tmin <= th);
    const bool ovf  = pass && (cnt > 3);

    unsigned myc[3];
    int mync = 0;
    if (pass && !ovf) {
        const uint32_t* w = (const uint32_t*)&e;
        #pragma unroll
        for (int j = 0; j < 3; j++) {
            if (j < cnt) {
                unsigned cw = w[1 + j];
                float v = __half2float(__ushort_as_half((unsigned short)(cw & 0xFFFFu)));
                if (v <= th) { myc[mync] = cw; mync++; }
            }
        }
    }
    const unsigned ovfmask = __ballot_sync(0xFFFFFFFFu, ovf);
    int totc = mync;
    #pragma unroll
    for (int o = 16; o; o >>= 1) totc += __shfl_xor_sync(0xFFFFFFFFu, totc, o);

    if (ovfmask == 0u && totc == 1) {
        unsigned bl = __ballot_sync(0xFFFFFFFFu, mync > 0);
        int src = __ffs(bl) - 1;
        unsigned cw = __shfl_sync(0xFFFFFFFFu, myc[0], src);
        if (lane == 0) g_idx[n] = cw >> 16;
        return;
    }

    // slow path: exact fp32 recheck
    const float xn = g_xnorm[n];
    const float4* xr = (const float4*)(g_Xt + (size_t)n * DD);
    float4 xa = xr[lane];
    float4 xb = xr[32 + lane];

    ull bestp = 0xFFFFFFFFFFFFFFFFULL;
    int rem = mync;
    unsigned act;
    while ((act = __ballot_sync(0xFFFFFFFFu, rem > 0)) != 0) {
        int leader = __ffs(act) - 1;
        unsigned cwl = (rem == 3) ? myc[2] : (rem == 2) ? myc[1] : myc[0];
        unsigned cw = __shfl_sync(0xFFFFFFFFu, cwl, leader);
        if (lane == leader) rem--;
        ull p = recheck_one((int)(cw >> 16), xn, xa, xb, cb);
        if (p < bestp) bestp = p;
    }
    unsigned om = ovfmask;
    while (om) {
        int tl = __ffs(om) - 1; om &= om - 1;
        for (int j = 0; j < 64; j++) {
            ull p = recheck_one(tl * 64 + j, xn, xa, xb, cb);
            if (p < bestp) bestp = p;
        }
    }
    if (lane == 0) g_idx[n] = (unsigned)(bestp & 0xFFFFFFFFULL);
}

// ---------------------------------------------------------
// quantize + straight-through + loss + indices (coalesced along t);
// last block finalizes the loss output (fused finalize).
__global__ void __launch_bounds__(256)
vq_quant_kernel(const float* __restrict__ lat, const float* __restrict__ cb,
                float* __restrict__ out) {
    extern __shared__ float qsm[];
    float*    q_s   = qsm;                             // [64][257]
    unsigned* idx_s = (unsigned*)(qsm + 64 * 257);     // [64]
    float*    red   = (float*)(idx_s + 64);            // [256]

    const int tid = threadIdx.x;
    const int cid = blockIdx.x;      // 0..511
    const int b   = cid >> 4;
    const int t0  = (cid & 15) << 6;

    if (tid < 64) {
        int n = b * TT + t0 + tid;
        unsigned k = g_idx[n];
        idx_s[tid] = k;
        out[OUT_IDX_OFF + n] = (float)k;
    }
    __syncthreads();

    {
        const float4* cb4 = (const float4*)cb;
        #pragma unroll
        for (int i = tid; i < 4096; i += 256) {
            int r = i >> 6, c4 = i & 63;
            float4 v = cb4[idx_s[r] * 64 + c4];
            float* q = q_s + r * 257 + c4 * 4;
            q[0] = v.x; q[1] = v.y; q[2] = v.z; q[3] = v.w;
        }
    }
    __syncthreads();

    const int tl = tid & 63;
    const int dg = tid >> 6;
    const int t  = t0 + tl;
    float lsum = 0.0f;
    #pragma unroll 8
    for (int dd = 0; dd < 64; dd++) {
        int d = dg * 64 + dd;
        size_t off = ((size_t)b * DD + d) * TT + t;
        float x = lat[off];
        float q = q_s[tl * 257 + d];
        float dq = __fsub_rn(q, x);
        out[OUT_Q_OFF + off] = __fadd_rn(x, dq);
        lsum = __fmaf_rn(dq, dq, lsum);
    }

    red[tid] = lsum;
    __syncthreads();
    for (int s = 128; s > 0; s >>= 1) {
        if (tid < s) red[tid] += red[tid + s];
        __syncthreads();
    }
    if (tid == 0) {
        atomicAdd(&g_loss, (double)red[0]);
        __threadfence();
        unsigned done = atomicAdd(&g_qdone, 1u);
        if (done == 511u) {
            double mean = g_loss / (double)((size_t)NN * DD);
            out[OUT_LOSS_OFF] = (float)(mean * 1.25);
            g_qdone = 0;
        }
    }
}

// ---------------------------------------------------------
extern "C" void kernel_launch(void* const* d_in, const int* in_sizes, int n_in,
                              void* d_out, int out_size) {
    const float* lat = (const float*)d_in[0];   // [32, 256, 1024]
    const float* cb  = (const float*)d_in[1];   // [1024, 256]
    float* out = (float*)d_out;

    const int QUANT_SMEM = (64 * 257 + 64 + 256) * 4;   // 67072 B

    cudaFuncSetAttribute(vq_mma_kernel,
                         cudaFuncAttributeMaxDynamicSharedMemorySize, SM_TOTM);
    cudaFuncSetAttribute(vq_quant_kernel,
                         cudaFuncAttributeMaxDynamicSharedMemorySize, QUANT_SMEM);

    vq_prep_b_kernel<<<KK, 256>>>(cb);
    vq_prep_a_kernel<<<1024, 256>>>(lat);

    dim3 grid(256, 8);
    vq_mma_kernel<<<grid, 256, SM_TOTM>>>();

    vq_select_kernel<<<NN / 8, 256>>>(cb);
    vq_quant_kernel<<<512, 256, QUANT_SMEM>>>(lat, cb, out);
}

// round 14
// speedup vs baseline: 1.0662x; 1.0662x over previous
#include <cuda_runtime.h>
#include <cuda_bf16.h>
#include <cuda_fp16.h>
#include <cstdint>

// Problem constants
#define BATCH 32
#define TT    1024
#define DD    256
#define KK    1024
#define NN    (BATCH*TT)
#define DT    (DD*TT)

#define OUT_Q_OFF    0
#define OUT_LOSS_OFF 8388608
#define OUT_IDX_OFF  8388609

typedef unsigned long long ull;

// -------- device scratch (no allocations allowed) --------
__device__ __half g_A2[(size_t)NN * DD];   // token-major fp16 latents
__device__ __half g_B2[(size_t)KK * DD];   // fp16 codebook
__device__ float  g_Xt[(size_t)NN * DD];   // token-major fp32 latents
__device__ __half g_s[(size_t)NN * KK];    // approx s = wn - 2*dot (fp16)
__device__ float  g_wnorm[KK];
__device__ float  g_xnorm[NN];
__device__ unsigned g_idx[NN];
__device__ double g_loss;
__device__ unsigned g_qdone;

// -------- PTX helpers --------
__device__ __forceinline__ uint32_t smem_u32(const void* p) {
    uint32_t a;
    asm("{ .reg .u64 t; cvta.to.shared.u64 t, %1; cvt.u32.u64 %0, t; }"
        : "=r"(a) : "l"(p));
    return a;
}
__device__ __forceinline__ void cp_async16(uint32_t s, const void* g) {
    asm volatile("cp.async.cg.shared.global [%0], [%1], 16;" :: "r"(s), "l"(g));
}
#define CP_COMMIT() asm volatile("cp.async.commit_group;")
#define CP_WAIT1()  asm volatile("cp.async.wait_group 1;")
#define CP_WAIT0()  asm volatile("cp.async.wait_group 0;")

#define LDSM_X4(r0, r1, r2, r3, addr) \
    asm volatile("ldmatrix.sync.aligned.m8n8.x4.shared.b16 {%0,%1,%2,%3}, [%4];" \
        : "=r"(r0), "=r"(r1), "=r"(r2), "=r"(r3) : "r"(addr))

#define MMA_F16(c, a, b0, b1) \
    asm volatile("mma.sync.aligned.m16n8k16.row.col.f32.f16.f16.f32 " \
        "{%0,%1,%2,%3}, {%4,%5,%6,%7}, {%8,%9}, {%0,%1,%2,%3};" \
        : "+f"((c)[0]), "+f"((c)[1]), "+f"((c)[2]), "+f"((c)[3]) \
        : "r"((a)[0]), "r"((a)[1]), "r"((a)[2]), "r"((a)[3]), "r"(b0), "r"(b1))

// ---------------------------------------------------------
// prep B: fp16 codebook + wnorm; zero loss + counter
__global__ void vq_prep_b_kernel(const float* __restrict__ cb) {
    __shared__ double sred[256];
    int k = blockIdx.x, d = threadIdx.x;
    float w = cb[k * DD + d];
    g_B2[(size_t)k * DD + d] = __float2half_rn(w);
    sred[d] = (double)w * (double)w;
    __syncthreads();
    for (int s = 128; s > 0; s >>= 1) {
        if (d < s) sred[d] += sred[d + s];
        __syncthreads();
    }
    if (d == 0) {
        g_wnorm[k] = (float)sred[0];
        if (k == 0) { g_loss = 0.0; g_qdone = 0; }
    }
}

// prep A: transpose latents to token-major fp32 + fp16, fused xnorm (fp64).
__global__ void __launch_bounds__(256)
vq_prep_a_kernel(const float* __restrict__ lat) {
    __shared__ float  s[256 * 33];
    __shared__ double pr[256];
    const int tid = threadIdx.x;
    const int b   = blockIdx.x >> 5;
    const int t0  = (blockIdx.x & 31) << 5;

    #pragma unroll
    for (int i = tid; i < 2048; i += 256) {
        int d = i >> 3, tq = i & 7;
        float4 v = *(const float4*)(lat + ((size_t)b * DD + d) * TT + t0 + tq * 4);
        s[d * 33 + tq * 4 + 0] = v.x;
        s[d * 33 + tq * 4 + 1] = v.y;
        s[d * 33 + tq * 4 + 2] = v.z;
        s[d * 33 + tq * 4 + 3] = v.w;
    }
    __syncthreads();

    const int d = tid;
    #pragma unroll 4
    for (int tl = 0; tl < 32; tl++) {
        size_t n = (size_t)b * TT + t0 + tl;
        float x = s[d * 33 + tl];
        g_A2[n * DD + d] = __float2half_rn(x);
        g_Xt[n * DD + d] = x;
    }

    const int tk = tid & 31, dg = tid >> 5;
    double ssum = 0.0;
    #pragma unroll 8
    for (int dd = 0; dd < 32; dd++) {
        float v = s[(dg * 32 + dd) * 33 + tk];
        ssum += (double)v * (double)v;
    }
    pr[tid] = ssum;
    __syncthreads();
    if (tid < 32) {
        double tot = 0.0;
        #pragma unroll
        for (int j = 0; j < 8; j++) tot += pr[j * 32 + tid];
        g_xnorm[b * TT + t0 + tid] = (float)tot;
    }
}

// ---------------------------------------------------------
// main GEMM: CTA 128 tokens x 128 codes, K=256 in 4 chunks of 64,
// mma.sync m16n8k16 fp16, double-buffered cp.async tiles (SW128 swizzle).
// Epilogue writes fp16 surrogate s = wn - 2*dot.
#define SM_WN    65536
#define SM_TOTM  66048

__device__ __forceinline__ void issue_chunk(uint32_t sb, int bufsel, int chunk,
                                            int n0, int kb, int tid) {
    uint32_t Ab = sb + (uint32_t)bufsel * 32768u;
    #pragma unroll
    for (int u = 0; u < 4; u++) {
        int j = tid + u * 256;
        int r = j >> 3, g8 = j & 7;
        cp_async16(Ab + (uint32_t)(r * 128 + ((g8 * 16) ^ ((r & 7) << 4))),
                   g_A2 + (size_t)(n0 + r) * DD + chunk * 64 + g8 * 8);
    }
    #pragma unroll
    for (int u = 0; u < 4; u++) {
        int j = tid + u * 256;
        int r = j >> 3, g8 = j & 7;
        cp_async16(Ab + 16384u + (uint32_t)(r * 128 + ((g8 * 16) ^ ((r & 7) << 4))),
                   g_B2 + (size_t)(kb + r) * DD + chunk * 64 + g8 * 8);
    }
}

__global__ void __launch_bounds__(256, 2)
vq_mma_kernel() {
    extern __shared__ char smc[];
    const uint32_t sb = smem_u32(smc);
    float* wn_s = (float*)(smc + SM_WN);

    const int tid  = threadIdx.x;
    const int lane = tid & 31;
    const int warp = tid >> 5;
    const int wm   = warp >> 1;        // 0..3
    const int wnn  = warp & 1;         // 0..1
    const int n0   = blockIdx.x << 7;  // token base
    const int kb   = blockIdx.y << 7;  // code base

    if (tid < 128) wn_s[tid] = g_wnorm[kb + tid];

    issue_chunk(sb, 0, 0, n0, kb, tid); CP_COMMIT();
    issue_chunk(sb, 1, 1, n0, kb, tid); CP_COMMIT();

    float acc[2][8][4];
    #pragma unroll
    for (int i = 0; i < 2; i++)
        #pragma unroll
        for (int j = 0; j < 8; j++)
            #pragma unroll
            for (int e = 0; e < 4; e++) acc[i][j][e] = 0.0f;

    const int arow   = (lane & 7) | (((lane >> 3) & 1) << 3);
    const int akoffB = (lane >> 4) << 4;
    const int brow   = (lane & 7) | ((lane >> 4) << 3);
    const int bkoffB = ((lane >> 3) & 1) << 4;

    for (int c = 0; c < 4; c++) {
        if (c < 3) { CP_WAIT1(); } else { CP_WAIT0(); }
        __syncthreads();

        uint32_t Ab = sb + (uint32_t)(c & 1) * 32768u;
        uint32_t Bb = Ab + 16384u;

        #pragma unroll
        for (int k16 = 0; k16 < 4; k16++) {
            uint32_t a[2][4];
            #pragma unroll
            for (int mt = 0; mt < 2; mt++) {
                int r = wm * 32 + mt * 16 + arow;
                uint32_t ad = Ab + (uint32_t)(r * 128 +
                              ((k16 * 32 + akoffB) ^ ((r & 7) << 4)));
                LDSM_X4(a[mt][0], a[mt][1], a[mt][2], a[mt][3], ad);
            }
            uint32_t bf[8][2];
            #pragma unroll
            for (int p = 0; p < 4; p++) {
                int nl = wnn * 64 + p * 16 + brow;
                uint32_t bd = Bb + (uint32_t)(nl * 128 +
                              ((k16 * 32 + bkoffB) ^ ((nl & 7) << 4)));
                LDSM_X4(bf[2 * p][0], bf[2 * p][1], bf[2 * p + 1][0], bf[2 * p + 1][1], bd);
            }
            #pragma unroll
            for (int mt = 0; mt < 2; mt++)
                #pragma unroll
                for (int n8 = 0; n8 < 8; n8++)
                    MMA_F16(acc[mt][n8], a[mt], bf[n8][0], bf[n8][1]);
        }
        __syncthreads();
        if (c < 2) { issue_chunk(sb, c & 1, c + 2, n0, kb, tid); CP_COMMIT(); }
    }

    // ---- epilogue: s = wn - 2*dot, fp16 pairs -> g_s ----
    const int g  = lane >> 2;
    const int qc = lane & 3;
    #pragma unroll
    for (int mt = 0; mt < 2; mt++) {
        #pragma unroll
        for (int h = 0; h < 2; h++) {
            int rl = wm * 32 + mt * 16 + h * 8 + g;
            uint32_t* rowp = (uint32_t*)(g_s + (size_t)(n0 + rl) * KK + kb + wnn * 64);
            #pragma unroll
            for (int n8 = 0; n8 < 8; n8++) {
                int cl0 = wnn * 64 + n8 * 8 + qc * 2;
                float s0 = __fmaf_rn(-2.0f, acc[mt][n8][h * 2 + 0], wn_s[cl0]);
                float s1 = __fmaf_rn(-2.0f, acc[mt][n8][h * 2 + 1], wn_s[cl0 + 1]);
                __half2 hp = __floats2half2_rn(s0, s1);
                rowp[n8 * 4 + qc] = *(uint32_t*)&hp;
            }
        }
    }
}

// ---------------------------------------------------------
// select: warp per token. hmin2 scan of fp16 s row, chunk-prefiltered
// candidate mask; single-candidate fast path exits BEFORE touching g_Xt;
// else exact fp32 recheck with the reference dist formula + packed
// (dist,k) first-index tie-break.
// Bound: fp16-gemm (6.1e-4) + fp16 store (4.9e-4) -> 2E ~ 2.3e-3;
// EPS = 4e-3 gives 1.7x margin.
#define EPS_SEL 4e-3f

__global__ void __launch_bounds__(256)
vq_select_kernel(const float* __restrict__ cb) {
    const int wid  = threadIdx.x >> 5;
    const int lane = threadIdx.x & 31;
    const int n    = blockIdx.x * 8 + wid;

    const uint4* srow = (const uint4*)(g_s + (size_t)n * KK);
    uint4 v[4];
    __half2 m2 = __floats2half2_rn(6.0e4f, 6.0e4f);
    #pragma unroll
    for (int j = 0; j < 4; j++) {
        v[j] = srow[lane + j * 32];
        const __half2* h = (const __half2*)&v[j];
        m2 = __hmin2(m2, __hmin2(__hmin2(h[0], h[1]), __hmin2(h[2], h[3])));
    }
    float m = fminf(__low2float(m2), __high2float(m2));
    #pragma unroll
    for (int o = 16; o; o >>= 1) m = fminf(m, __shfl_xor_sync(0xFFFFFFFFu, m, o));
    const float thresh = m + EPS_SEL;

    unsigned cmask = 0;
    #pragma unroll
    for (int j = 0; j < 4; j++) {
        const __half2* h = (const __half2*)&v[j];
        __half2 cm2 = __hmin2(__hmin2(h[0], h[1]), __hmin2(h[2], h[3]));
        float cmin = fminf(__low2float(cm2), __high2float(cm2));
        if (cmin <= thresh) {
            #pragma unroll
            for (int q = 0; q < 4; q++) {
                float2 f = __half22float2(h[q]);
                if (f.x <= thresh) cmask |= 1u << (j * 8 + q * 2 + 0);
                if (f.y <= thresh) cmask |= 1u << (j * 8 + q * 2 + 1);
            }
        }
    }

    // fast path: exactly one candidate warp-wide -> done, no x-row read
    {
        int cnt = __popc(cmask);
        #pragma unroll
        for (int o = 16; o; o >>= 1) cnt += __shfl_xor_sync(0xFFFFFFFFu, cnt, o);
        if (cnt == 1) {
            unsigned bl = __ballot_sync(0xFFFFFFFFu, cmask != 0);
            int src = __ffs(bl) - 1;
            int bpos = __shfl_sync(0xFFFFFFFFu, cmask ? (__ffs(cmask) - 1) : 0, src);
            int k = (src + (bpos >> 3) * 32) * 8 + (bpos & 7);
            if (lane == 0) g_idx[n] = (unsigned)k;
            return;
        }
    }

    // slow path: exact fp32 recheck of every candidate
    const float xn = g_xnorm[n];
    const float4* xr = (const float4*)(g_Xt + (size_t)n * DD);
    float4 xa = xr[lane];
    float4 xb = xr[32 + lane];

    ull bestp = 0xFFFFFFFFFFFFFFFFULL;
    unsigned act;
    while ((act = __ballot_sync(0xFFFFFFFFu, cmask != 0)) != 0) {
        int leader = __ffs(act) - 1;
        int k = 0;
        if (lane == leader) {
            int bpos = __ffs(cmask) - 1;
            cmask &= cmask - 1;
            k = (lane + (bpos >> 3) * 32) * 8 + (bpos & 7);
        }
        k = __shfl_sync(0xFFFFFFFFu, k, leader);

        const float4* wr = (const float4*)(cb + (size_t)k * DD);
        float4 wa = wr[lane];
        float4 wb = wr[32 + lane];
        float s = 0.0f;
        s = __fmaf_rn(xa.x, wa.x, s); s = __fmaf_rn(xa.y, wa.y, s);
        s = __fmaf_rn(xa.z, wa.z, s); s = __fmaf_rn(xa.w, wa.w, s);
        s = __fmaf_rn(xb.x, wb.x, s); s = __fmaf_rn(xb.y, wb.y, s);
        s = __fmaf_rn(xb.z, wb.z, s); s = __fmaf_rn(xb.w, wb.w, s);
        #pragma unroll
        for (int o = 16; o; o >>= 1) s = __fadd_rn(s, __shfl_xor_sync(0xFFFFFFFFu, s, o));

        float dist = __fadd_rn(__fmaf_rn(-2.0f, s, xn), g_wnorm[k]);
        ull p = ((ull)__float_as_uint(dist) << 32) | (unsigned)k;
        if (p < bestp) bestp = p;
    }
    if (lane == 0) g_idx[n] = (unsigned)(bestp & 0xFFFFFFFFULL);
}

// ---------------------------------------------------------
// quantize + straight-through + loss + indices (coalesced along t);
// last block finalizes the loss output (fused finalize).
__global__ void __launch_bounds__(256)
vq_quant_kernel(const float* __restrict__ lat, const float* __restrict__ cb,
                float* __restrict__ out) {
    extern __shared__ float qsm[];
    float*    q_s   = qsm;                             // [64][257]
    unsigned* idx_s = (unsigned*)(qsm + 64 * 257);     // [64]
    float*    red   = (float*)(idx_s + 64);            // [256]

    const int tid = threadIdx.x;
    const int cid = blockIdx.x;      // 0..511
    const int b   = cid >> 4;
    const int t0  = (cid & 15) << 6;

    if (tid < 64) {
        int n = b * TT + t0 + tid;
        unsigned k = g_idx[n];
        idx_s[tid] = k;
        out[OUT_IDX_OFF + n] = (float)k;
    }
    __syncthreads();

    {
        const float4* cb4 = (const float4*)cb;
        #pragma unroll
        for (int i = tid; i < 4096; i += 256) {
            int r = i >> 6, c4 = i & 63;
            float4 v = cb4[idx_s[r] * 64 + c4];
            float* q = q_s + r * 257 + c4 * 4;
            q[0] = v.x; q[1] = v.y; q[2] = v.z; q[3] = v.w;
        }
    }
    __syncthreads();

    const int tl = tid & 63;
    const int dg = tid >> 6;
    const int t  = t0 + tl;
    float lsum = 0.0f;
    #pragma unroll 8
    for (int dd = 0; dd < 64; dd++) {
        int d = dg * 64 + dd;
        size_t off = ((size_t)b * DD + d) * TT + t;
        float x = lat[off];
        float q = q_s[tl * 257 + d];
        float dq = __fsub_rn(q, x);
        out[OUT_Q_OFF + off] = __fadd_rn(x, dq);
        lsum = __fmaf_rn(dq, dq, lsum);
    }

    red[tid] = lsum;
    __syncthreads();
    for (int s = 128; s > 0; s >>= 1) {
        if (tid < s) red[tid] += red[tid + s];
        __syncthreads();
    }
    if (tid == 0) {
        atomicAdd(&g_loss, (double)red[0]);
        __threadfence();
        unsigned done = atomicAdd(&g_qdone, 1u);
        if (done == 511u) {                 // last block finalizes
            double mean = g_loss / (double)((size_t)NN * DD);
            out[OUT_LOSS_OFF] = (float)(mean * 1.25);
            g_qdone = 0;                    // reset for next graph replay
        }
    }
}

// ---------------------------------------------------------
extern "C" void kernel_launch(void* const* d_in, const int* in_sizes, int n_in,
                              void* d_out, int out_size) {
    const float* lat = (const float*)d_in[0];   // [32, 256, 1024]
    const float* cb  = (const float*)d_in[1];   // [1024, 256]
    float* out = (float*)d_out;

    const int QUANT_SMEM = (64 * 257 + 64 + 256) * 4;   // 67072 B

    cudaFuncSetAttribute(vq_mma_kernel,
                         cudaFuncAttributeMaxDynamicSharedMemorySize, SM_TOTM);
    cudaFuncSetAttribute(vq_quant_kernel,
                         cudaFuncAttributeMaxDynamicSharedMemorySize, QUANT_SMEM);

    vq_prep_b_kernel<<<KK, 256>>>(cb);
    vq_prep_a_kernel<<<1024, 256>>>(lat);

    dim3 grid(256, 8);
    vq_mma_kernel<<<grid, 256, SM_TOTM>>>();

    vq_select_kernel<<<NN / 8, 256>>>(cb);
    vq_quant_kernel<<<512, 256, QUANT_SMEM>>>(lat, cb, out);
}